// round 16
// baseline (speedup 1.0000x reference)
#include <cuda_runtime.h>
#include <math.h>

#define EPS2_F 1e-16f   /* EPS^2: clamp squared norm so n = d*rsqrt(d) >= 1e-8 */

// Global accumulators + completion ticket. Zero at module load; the LAST block
// resets them each launch, so every graph replay starts from zero.
__device__ double   g_acc[6];
__device__ unsigned g_ticket;

struct Q4 { float w, x, y, z; };
struct Row { float f[6]; };

__device__ __forceinline__ Q4 qmult(const Q4 a, const Q4 b) {
    Q4 r;
    r.w = a.w * b.w - a.x * b.x - a.y * b.y - a.z * b.z;
    r.x = a.w * b.x + a.x * b.w + a.y * b.z - a.z * b.y;
    r.y = a.w * b.y - a.x * b.z + a.y * b.w + a.z * b.x;
    r.z = a.w * b.z + a.x * b.y - a.y * b.x + a.z * b.w;
    return r;
}

__device__ __forceinline__ Q4 qexp3(float vx, float vy, float vz) {
    float d  = fmaxf(vx * vx + vy * vy + vz * vz, EPS2_F);
    float rn = rsqrtf(d);        // == 1/n
    float n  = d * rn;           // sqrt(d)
    float s  = __sinf(n) * rn;
    Q4 r;
    r.w = __cosf(n);
    r.x = vx * s; r.y = vy * s; r.z = vz * s;
    return r;
}

// Branchless acos, |err| ~1e-7 (A&S 4.4.46 7-term). Input must be in [-1, 1].
__device__ __forceinline__ float facos(float x) {
    float ax = fabsf(x);
    float p = fmaf(ax, -0.0012624911f,  0.0066700901f);
    p = fmaf(p, ax, -0.0170881256f);
    p = fmaf(p, ax,  0.0308918810f);
    p = fmaf(p, ax, -0.0501743046f);
    p = fmaf(p, ax,  0.0889789874f);
    p = fmaf(p, ax, -0.2145988016f);
    p = fmaf(p, ax,  1.5707963050f);
    float t = fmaxf(1.0f - ax, 0.0f);
    float s = t * rsqrtf(fmaxf(t, 1e-30f));   // sqrt(t), safe at t=0
    float f = s * p;
    return (x >= 0.0f) ? f : (3.14159265359f - f);
}

__device__ __forceinline__ void qlog3(const Q4 q, float& ox, float& oy, float& oz) {
    float d  = fmaxf(q.x * q.x + q.y * q.y + q.z * q.z, EPS2_F);
    float rn = rsqrtf(d);
    float f  = facos(fminf(fmaxf(q.w, -1.0f), 1.0f)) * rn;
    ox = q.x * f; oy = q.y * f; oz = q.z * f;
}

// One (t -> t+1) VO + IMU contribution.
// imu_ori_shift: qexp outputs are unit quaternions, so q0^-1*(q0*dq) == dq and
// qlog(dq) == 0.5 * dt * ang_vel exactly.
__device__ __forceinline__ void vo_term(
    const Row& p0, const Row& p1, const Row& g0, const Row& g1,
    float ax, float ay, float az, float vx, float vy, float vz,
    float wx, float wy, float wz, float ts0, float ts1,
    const Q4& q0, const Q4& q1,
    float& s2, float& s3, float& s4, float& s5)
{
    Q4 q0i; q0i.w = q0.w; q0i.x = -q0.x; q0i.y = -q0.y; q0i.z = -q0.z;

    // targ_imu_q = qlog(q0^-1 * q1)
    Q4 rel = qmult(q0i, q1);
    float tiqx, tiqy, tiqz;
    qlog3(rel, tiqx, tiqy, tiqz);

    float dt = (ts1 - ts0) * 1e-9f;
    float itx = vx * dt + 0.5f * ax * dt * dt;
    float ity = vy * dt + 0.5f * ay * dt * dt;
    float itz = vz * dt + 0.5f * az * dt * dt;

    // imu_ori_shift = 0.5 * dt * ang_vel
    float hdt = 0.5f * dt;
    float iox = wx * hdt, ioy = wy * hdt, ioz = wz * hdt;

    float pvx = p1.f[0] - p0.f[0], pvy = p1.f[1] - p0.f[1], pvz = p1.f[2] - p0.f[2];
    float pqx = p1.f[3] - p0.f[3], pqy = p1.f[4] - p0.f[4], pqz = p1.f[5] - p0.f[5];
    float tvx = g1.f[0] - g0.f[0], tvy = g1.f[1] - g0.f[1], tvz = g1.f[2] - g0.f[2];
    float tqx = g1.f[3] - g0.f[3], tqy = g1.f[4] - g0.f[4], tqz = g1.f[5] - g0.f[5];

    s2 += fabsf(pvx - tvx) + fabsf(pvy - tvy) + fabsf(pvz - tvz);
    s3 += fabsf(pqx - tqx) + fabsf(pqy - tqy) + fabsf(pqz - tqz);
    s4 += fabsf(pvx - itx) + fabsf(pvy - ity) + fabsf(pvz - itz);
    s5 += fabsf(tiqx - iox) + fabsf(tiqy - ioy) + fabsf(tiqz - ioz);
}

__global__ void __launch_bounds__(256, 4) loss_kernel(
    const float* __restrict__ pred,
    const float* __restrict__ targ,
    const float* __restrict__ imu,
    const float* __restrict__ sax, const float* __restrict__ saq,
    const float* __restrict__ srx, const float* __restrict__ srq,
    float* __restrict__ out,
    int npairs, double inv_abs, double inv_vo)
{
    const int tid    = threadIdx.x;
    const int stride = gridDim.x * blockDim.x;

    float s0 = 0.f, s1 = 0.f, s2 = 0.f, s3 = 0.f, s4 = 0.f, s5 = 0.f;

    // Persistent grid-stride loop sized to exactly one residency wave
    // (grid = SMs x CTAs/SM), so there is no partial-wave tail.
    for (int j = blockIdx.x * 256 + tid; j < npairs; j += stride) {
        // Boundary pair index clamped so ALL loads are in-bounds and branch-
        // free; the only thread where the clamp changes the address has
        // has2 == false, so its garbage result is never accumulated.
        const int bj = (j < npairs - 1) ? j : (npairs - 2);
        const bool has2 = (((2 * j + 1) & 1023) != 1023);   // T = 1024

        // ---- one straight-line block of independent loads (max MLP) ----
        const float4* p4 = reinterpret_cast<const float4*>(pred) + (size_t)3 * j;
        const float4* t4 = reinterpret_cast<const float4*>(targ) + (size_t)3 * j;
        float4 pa = p4[0], pb = p4[1], pc = p4[2];
        float4 ta = t4[0], tb = t4[1], tc = t4[2];

        const float4* i4 = reinterpret_cast<const float4*>(imu) + (size_t)5 * j;
        float4 ia = i4[0], ib = i4[1], ic = i4[2], id4 = i4[3], ie4 = i4[4];

        float4 pdq = reinterpret_cast<const float4*>(pred)[(size_t)3 * bj + 3];
        float2 pe2 = reinterpret_cast<const float2*>(pred)[(size_t)6 * bj + 8];
        float4 tdq = reinterpret_cast<const float4*>(targ)[(size_t)3 * bj + 3];
        float2 te2 = reinterpret_cast<const float2*>(targ)[(size_t)6 * bj + 8];
        float  ts2 = imu[(size_t)20 * bj + 29];    // ts of row 2bj+2

        Row p0 = {{pa.x, pa.y, pa.z, pa.w, pb.x, pb.y}};
        Row p1 = {{pb.z, pb.w, pc.x, pc.y, pc.z, pc.w}};
        Row g0 = {{ta.x, ta.y, ta.z, ta.w, tb.x, tb.y}};
        Row g1 = {{tb.z, tb.w, tc.x, tc.y, tc.z, tc.w}};
        Row p2 = {{pdq.x, pdq.y, pdq.z, pdq.w, pe2.x, pe2.y}};
        Row g2 = {{tdq.x, tdq.y, tdq.z, tdq.w, te2.x, te2.y}};

        // abs loss for both rows
        s0 += fabsf(p0.f[0]-g0.f[0]) + fabsf(p0.f[1]-g0.f[1]) + fabsf(p0.f[2]-g0.f[2])
            + fabsf(p1.f[0]-g1.f[0]) + fabsf(p1.f[1]-g1.f[1]) + fabsf(p1.f[2]-g1.f[2]);
        s1 += fabsf(p0.f[3]-g0.f[3]) + fabsf(p0.f[4]-g0.f[4]) + fabsf(p0.f[5]-g0.f[5])
            + fabsf(p1.f[3]-g1.f[3]) + fabsf(p1.f[4]-g1.f[4]) + fabsf(p1.f[5]-g1.f[5]);

        // qexp: 3 per pair (middle one shared between the two vo terms)
        Q4 qe0 = qexp3(g0.f[3], g0.f[4], g0.f[5]);
        Q4 qe1 = qexp3(g1.f[3], g1.f[4], g1.f[5]);
        Q4 qe2 = qexp3(g2.f[3], g2.f[4], g2.f[5]);

        // imu row 2j   = {ia.x,ia.y,ia.z, ia.w,ib.x,ib.y, ib.z,ib.w,ic.x, ic.y}
        // imu row 2j+1 = {ic.z,ic.w,id4.x, id4.y,id4.z,id4.w, ie4.x,ie4.y,ie4.z, ie4.w}
        vo_term(p0, p1, g0, g1,
                ia.x, ia.y, ia.z,        // accel
                ia.w, ib.x, ib.y,        // vel
                ib.z, ib.w, ic.x,        // ang_vel
                ic.y, ie4.w,             // ts0, ts1
                qe0, qe1, s2, s3, s4, s5);

        // element 2j+1 -> 2j+2: compute unconditionally, accumulate predicated
        float u2 = 0.f, u3 = 0.f, u4 = 0.f, u5 = 0.f;
        vo_term(p1, p2, g1, g2,
                ic.z, ic.w, id4.x,   // accel
                id4.y, id4.z, id4.w, // vel
                ie4.x, ie4.y, ie4.z, // ang_vel
                ie4.w, ts2,          // ts1, ts2
                qe1, qe2, u2, u3, u4, u5);
        if (has2) { s2 += u2; s3 += u3; s4 += u4; s5 += u5; }
    }

    // ---- block reduction (once per block) ----
    const unsigned FULL = 0xffffffffu;
    #pragma unroll
    for (int o = 16; o > 0; o >>= 1) {
        s0 += __shfl_xor_sync(FULL, s0, o);
        s1 += __shfl_xor_sync(FULL, s1, o);
        s2 += __shfl_xor_sync(FULL, s2, o);
        s3 += __shfl_xor_sync(FULL, s3, o);
        s4 += __shfl_xor_sync(FULL, s4, o);
        s5 += __shfl_xor_sync(FULL, s5, o);
    }

    __shared__ float shred[8 * 6];
    __shared__ bool  is_last;
    int wid  = tid >> 5;
    int lane = tid & 31;
    if (lane == 0) {
        shred[wid * 6 + 0] = s0; shred[wid * 6 + 1] = s1; shred[wid * 6 + 2] = s2;
        shred[wid * 6 + 3] = s3; shred[wid * 6 + 4] = s4; shred[wid * 6 + 5] = s5;
    }
    __syncthreads();

    if (tid == 0) {
        float a0 = 0, a1 = 0, a2 = 0, a3 = 0, a4 = 0, a5 = 0;
        #pragma unroll
        for (int w = 0; w < 8; w++) {
            a0 += shred[w * 6 + 0]; a1 += shred[w * 6 + 1]; a2 += shred[w * 6 + 2];
            a3 += shred[w * 6 + 3]; a4 += shred[w * 6 + 4]; a5 += shred[w * 6 + 5];
        }
        atomicAdd(&g_acc[0], (double)a0); atomicAdd(&g_acc[1], (double)a1);
        atomicAdd(&g_acc[2], (double)a2); atomicAdd(&g_acc[3], (double)a3);
        atomicAdd(&g_acc[4], (double)a4); atomicAdd(&g_acc[5], (double)a5);
        __threadfence();
        unsigned ticket = atomicAdd(&g_ticket, 1u);
        is_last = (ticket == gridDim.x - 1);
    }
    __syncthreads();

    if (is_last && tid == 0) {
        __threadfence();
        double m0 = g_acc[0], m1d = g_acc[1], m2d = g_acc[2];
        double m3d = g_acc[3], m4d = g_acc[4], m5d = g_acc[5];

        float m1 = (float)(m0  * inv_abs);
        float m2 = (float)(m1d * inv_abs);
        float m3 = (float)(m2d * inv_vo);
        float m4 = (float)(m3d * inv_vo);
        float m5 = (float)(m4d * inv_vo);
        float m6 = (float)(m5d * inv_vo);

        float A = sax[0], B = saq[0], X = srx[0], Y = srq[0];
        float abs_loss = expf(-A) * m1 + A + expf(-B) * m2 + B;
        float vo_loss  = expf(-X) * m3 + X + expf(-Y) * m4 + Y;
        float imu_loss = expf(-X) * m5 + X + expf(-Y) * m6 + Y;
        out[0] = abs_loss + vo_loss + imu_loss;

        g_acc[0] = 0.0; g_acc[1] = 0.0; g_acc[2] = 0.0;
        g_acc[3] = 0.0; g_acc[4] = 0.0; g_acc[5] = 0.0;
        g_ticket = 0u;
        __threadfence();
    }
}

extern "C" void kernel_launch(void* const* d_in, const int* in_sizes, int n_in,
                              void* d_out, int out_size)
{
    const float* pred = (const float*)d_in[0];
    const float* targ = (const float*)d_in[1];
    const float* imu  = (const float*)d_in[2];
    const float* sax  = (const float*)d_in[3];
    const float* saq  = (const float*)d_in[4];
    const float* srx  = (const float*)d_in[5];
    const float* srq  = (const float*)d_in[6];

    const int T = 1024;
    const int total = in_sizes[0] / 6;          // N*T (even)
    const long long N = total / T;
    const int npairs = total >> 1;

    // Exactly one residency wave: 152 SMs x 4 CTAs/SM at <=64 regs/thread.
    int blocks = 152 * 4;
    int maxb = (npairs + 255) / 256;
    if (blocks > maxb) blocks = maxb;

    double inv_abs = 1.0 / ((double)total * 3.0);
    double inv_vo  = 1.0 / ((double)N * (double)(T - 1) * 3.0);

    loss_kernel<<<blocks, 256>>>(pred, targ, imu, sax, saq, srx, srq,
                                 (float*)d_out, npairs, inv_abs, inv_vo);
}

// round 17
// speedup vs baseline: 1.0643x; 1.0643x over previous
#include <cuda_runtime.h>
#include <math.h>

#define EPS2_F 1e-16f   /* EPS^2: clamp squared norm so n = d*rsqrt(d) >= 1e-8 */

// Global accumulators + completion ticket. Zero at module load; the LAST block
// resets them each launch, so every graph replay starts from zero.
__device__ double   g_acc[6];
__device__ unsigned g_ticket;

struct Q4 { float w, x, y, z; };
struct Row { float f[6]; };
struct Sums6 { float s0, s1, s2, s3, s4, s5; };

__device__ __forceinline__ Q4 qmult(const Q4 a, const Q4 b) {
    Q4 r;
    r.w = a.w * b.w - a.x * b.x - a.y * b.y - a.z * b.z;
    r.x = a.w * b.x + a.x * b.w + a.y * b.z - a.z * b.y;
    r.y = a.w * b.y - a.x * b.z + a.y * b.w + a.z * b.x;
    r.z = a.w * b.z + a.x * b.y - a.y * b.x + a.z * b.w;
    return r;
}

__device__ __forceinline__ Q4 qexp3(float vx, float vy, float vz) {
    float d  = fmaxf(vx * vx + vy * vy + vz * vz, EPS2_F);
    float rn = rsqrtf(d);        // == 1/n
    float n  = d * rn;           // sqrt(d)
    float s  = __sinf(n) * rn;
    Q4 r;
    r.w = __cosf(n);
    r.x = vx * s; r.y = vy * s; r.z = vz * s;
    return r;
}

// Branchless acos, |err| ~1e-7 (A&S 4.4.46 7-term). Input must be in [-1, 1].
__device__ __forceinline__ float facos(float x) {
    float ax = fabsf(x);
    float p = fmaf(ax, -0.0012624911f,  0.0066700901f);
    p = fmaf(p, ax, -0.0170881256f);
    p = fmaf(p, ax,  0.0308918810f);
    p = fmaf(p, ax, -0.0501743046f);
    p = fmaf(p, ax,  0.0889789874f);
    p = fmaf(p, ax, -0.2145988016f);
    p = fmaf(p, ax,  1.5707963050f);
    float t = fmaxf(1.0f - ax, 0.0f);
    float s = t * rsqrtf(fmaxf(t, 1e-30f));   // sqrt(t), safe at t=0
    float f = s * p;
    return (x >= 0.0f) ? f : (3.14159265359f - f);
}

__device__ __forceinline__ void qlog3(const Q4 q, float& ox, float& oy, float& oz) {
    float d  = fmaxf(q.x * q.x + q.y * q.y + q.z * q.z, EPS2_F);
    float rn = rsqrtf(d);
    float f  = facos(fminf(fmaxf(q.w, -1.0f), 1.0f)) * rn;
    ox = q.x * f; oy = q.y * f; oz = q.z * f;
}

// One (t -> t+1) VO + IMU contribution.
// imu_ori_shift: qexp outputs are unit quaternions, so q0^-1*(q0*dq) == dq and
// qlog(dq) == 0.5 * dt * ang_vel exactly.
__device__ __forceinline__ void vo_term(
    const Row& p0, const Row& p1, const Row& g0, const Row& g1,
    float ax, float ay, float az, float vx, float vy, float vz,
    float wx, float wy, float wz, float ts0, float ts1,
    const Q4& q0, const Q4& q1,
    float& s2, float& s3, float& s4, float& s5)
{
    Q4 q0i; q0i.w = q0.w; q0i.x = -q0.x; q0i.y = -q0.y; q0i.z = -q0.z;

    // targ_imu_q = qlog(q0^-1 * q1)
    Q4 rel = qmult(q0i, q1);
    float tiqx, tiqy, tiqz;
    qlog3(rel, tiqx, tiqy, tiqz);

    float dt = (ts1 - ts0) * 1e-9f;
    float itx = vx * dt + 0.5f * ax * dt * dt;
    float ity = vy * dt + 0.5f * ay * dt * dt;
    float itz = vz * dt + 0.5f * az * dt * dt;

    // imu_ori_shift = 0.5 * dt * ang_vel
    float hdt = 0.5f * dt;
    float iox = wx * hdt, ioy = wy * hdt, ioz = wz * hdt;

    float pvx = p1.f[0] - p0.f[0], pvy = p1.f[1] - p0.f[1], pvz = p1.f[2] - p0.f[2];
    float pqx = p1.f[3] - p0.f[3], pqy = p1.f[4] - p0.f[4], pqz = p1.f[5] - p0.f[5];
    float tvx = g1.f[0] - g0.f[0], tvy = g1.f[1] - g0.f[1], tvz = g1.f[2] - g0.f[2];
    float tqx = g1.f[3] - g0.f[3], tqy = g1.f[4] - g0.f[4], tqz = g1.f[5] - g0.f[5];

    s2 += fabsf(pvx - tvx) + fabsf(pvy - tvy) + fabsf(pvz - tvz);
    s3 += fabsf(pqx - tqx) + fabsf(pqy - tqy) + fabsf(pqz - tqz);
    s4 += fabsf(pvx - itx) + fabsf(pvy - ity) + fabsf(pvz - itz);
    s5 += fabsf(tiqx - iox) + fabsf(tiqy - ioy) + fabsf(tiqz - ioz);
}

// Full contribution of pair j (rows 2j, 2j+1) incl. boundary term. All loads
// in-bounds for any j in [0, npairs-1] via the internal clamp.
__device__ __forceinline__ Sums6 pair_body(
    const float* __restrict__ pred,
    const float* __restrict__ targ,
    const float* __restrict__ imu,
    int j, int npairs)
{
    const int bj = (j < npairs - 1) ? j : (npairs - 2);
    const bool has2 = (((2 * j + 1) & 1023) != 1023);   // T = 1024

    // ---- one straight-line block of independent loads (max MLP) ----
    const float4* p4 = reinterpret_cast<const float4*>(pred) + (size_t)3 * j;
    const float4* t4 = reinterpret_cast<const float4*>(targ) + (size_t)3 * j;
    float4 pa = p4[0], pb = p4[1], pc = p4[2];
    float4 ta = t4[0], tb = t4[1], tc = t4[2];

    const float4* i4 = reinterpret_cast<const float4*>(imu) + (size_t)5 * j;
    float4 ia = i4[0], ib = i4[1], ic = i4[2], id4 = i4[3], ie4 = i4[4];

    float4 pdq = reinterpret_cast<const float4*>(pred)[(size_t)3 * bj + 3];
    float2 pe2 = reinterpret_cast<const float2*>(pred)[(size_t)6 * bj + 8];
    float4 tdq = reinterpret_cast<const float4*>(targ)[(size_t)3 * bj + 3];
    float2 te2 = reinterpret_cast<const float2*>(targ)[(size_t)6 * bj + 8];
    float  ts2 = imu[(size_t)20 * bj + 29];    // ts of row 2bj+2

    Row p0 = {{pa.x, pa.y, pa.z, pa.w, pb.x, pb.y}};
    Row p1 = {{pb.z, pb.w, pc.x, pc.y, pc.z, pc.w}};
    Row g0 = {{ta.x, ta.y, ta.z, ta.w, tb.x, tb.y}};
    Row g1 = {{tb.z, tb.w, tc.x, tc.y, tc.z, tc.w}};
    Row p2 = {{pdq.x, pdq.y, pdq.z, pdq.w, pe2.x, pe2.y}};
    Row g2 = {{tdq.x, tdq.y, tdq.z, tdq.w, te2.x, te2.y}};

    Sums6 r;
    r.s2 = 0.f; r.s3 = 0.f; r.s4 = 0.f; r.s5 = 0.f;

    // abs loss for both rows
    r.s0 = fabsf(p0.f[0]-g0.f[0]) + fabsf(p0.f[1]-g0.f[1]) + fabsf(p0.f[2]-g0.f[2])
         + fabsf(p1.f[0]-g1.f[0]) + fabsf(p1.f[1]-g1.f[1]) + fabsf(p1.f[2]-g1.f[2]);
    r.s1 = fabsf(p0.f[3]-g0.f[3]) + fabsf(p0.f[4]-g0.f[4]) + fabsf(p0.f[5]-g0.f[5])
         + fabsf(p1.f[3]-g1.f[3]) + fabsf(p1.f[4]-g1.f[4]) + fabsf(p1.f[5]-g1.f[5]);

    // qexp: 3 per pair (middle one shared between the two vo terms)
    Q4 qe0 = qexp3(g0.f[3], g0.f[4], g0.f[5]);
    Q4 qe1 = qexp3(g1.f[3], g1.f[4], g1.f[5]);
    Q4 qe2 = qexp3(g2.f[3], g2.f[4], g2.f[5]);

    // imu row 2j   = {ia.x,ia.y,ia.z, ia.w,ib.x,ib.y, ib.z,ib.w,ic.x, ic.y}
    // imu row 2j+1 = {ic.z,ic.w,id4.x, id4.y,id4.z,id4.w, ie4.x,ie4.y,ie4.z, ie4.w}
    vo_term(p0, p1, g0, g1,
            ia.x, ia.y, ia.z,        // accel
            ia.w, ib.x, ib.y,        // vel
            ib.z, ib.w, ic.x,        // ang_vel
            ic.y, ie4.w,             // ts0, ts1
            qe0, qe1, r.s2, r.s3, r.s4, r.s5);

    // element 2j+1 -> 2j+2: compute unconditionally, accumulate predicated
    float u2 = 0.f, u3 = 0.f, u4 = 0.f, u5 = 0.f;
    vo_term(p1, p2, g1, g2,
            ic.z, ic.w, id4.x,   // accel
            id4.y, id4.z, id4.w, // vel
            ie4.x, ie4.y, ie4.z, // ang_vel
            ie4.w, ts2,          // ts1, ts2
            qe1, qe2, u2, u3, u4, u5);
    if (has2) { r.s2 += u2; r.s3 += u3; r.s4 += u4; r.s5 += u5; }
    return r;
}

__global__ void __launch_bounds__(256, 2) loss_kernel(
    const float* __restrict__ pred,
    const float* __restrict__ targ,
    const float* __restrict__ imu,
    const float* __restrict__ sax, const float* __restrict__ saq,
    const float* __restrict__ srx, const float* __restrict__ srq,
    float* __restrict__ out,
    int npairs, double inv_abs, double inv_vo)
{
    const int tid    = threadIdx.x;
    const int stride = gridDim.x * blockDim.x;

    float s0 = 0.f, s1 = 0.f, s2 = 0.f, s3 = 0.f, s4 = 0.f, s5 = 0.f;

    // Persistent one-wave grid; 2 independent pair-bodies per iteration for
    // double the per-thread MLP (both coalesced: indices j and j+stride).
    for (int j = blockIdx.x * 256 + tid; j < npairs; j += 2 * stride) {
        Sums6 a = pair_body(pred, targ, imu, j, npairs);

        int  j2   = j + stride;
        bool acc2 = (j2 < npairs);
        int  j2c  = acc2 ? j2 : (npairs - 1);   // in-bounds; garbage unaccumulated
        Sums6 b = pair_body(pred, targ, imu, j2c, npairs);

        s0 += a.s0; s1 += a.s1; s2 += a.s2;
        s3 += a.s3; s4 += a.s4; s5 += a.s5;
        if (acc2) {
            s0 += b.s0; s1 += b.s1; s2 += b.s2;
            s3 += b.s3; s4 += b.s4; s5 += b.s5;
        }
    }

    // ---- block reduction (once per block) ----
    const unsigned FULL = 0xffffffffu;
    #pragma unroll
    for (int o = 16; o > 0; o >>= 1) {
        s0 += __shfl_xor_sync(FULL, s0, o);
        s1 += __shfl_xor_sync(FULL, s1, o);
        s2 += __shfl_xor_sync(FULL, s2, o);
        s3 += __shfl_xor_sync(FULL, s3, o);
        s4 += __shfl_xor_sync(FULL, s4, o);
        s5 += __shfl_xor_sync(FULL, s5, o);
    }

    __shared__ float shred[8 * 6];
    __shared__ bool  is_last;
    int wid  = tid >> 5;
    int lane = tid & 31;
    if (lane == 0) {
        shred[wid * 6 + 0] = s0; shred[wid * 6 + 1] = s1; shred[wid * 6 + 2] = s2;
        shred[wid * 6 + 3] = s3; shred[wid * 6 + 4] = s4; shred[wid * 6 + 5] = s5;
    }
    __syncthreads();

    if (tid == 0) {
        float a0 = 0, a1 = 0, a2 = 0, a3 = 0, a4 = 0, a5 = 0;
        #pragma unroll
        for (int w = 0; w < 8; w++) {
            a0 += shred[w * 6 + 0]; a1 += shred[w * 6 + 1]; a2 += shred[w * 6 + 2];
            a3 += shred[w * 6 + 3]; a4 += shred[w * 6 + 4]; a5 += shred[w * 6 + 5];
        }
        atomicAdd(&g_acc[0], (double)a0); atomicAdd(&g_acc[1], (double)a1);
        atomicAdd(&g_acc[2], (double)a2); atomicAdd(&g_acc[3], (double)a3);
        atomicAdd(&g_acc[4], (double)a4); atomicAdd(&g_acc[5], (double)a5);
        __threadfence();
        unsigned ticket = atomicAdd(&g_ticket, 1u);
        is_last = (ticket == gridDim.x - 1);
    }
    __syncthreads();

    if (is_last && tid == 0) {
        __threadfence();
        double m0 = g_acc[0], m1d = g_acc[1], m2d = g_acc[2];
        double m3d = g_acc[3], m4d = g_acc[4], m5d = g_acc[5];

        float m1 = (float)(m0  * inv_abs);
        float m2 = (float)(m1d * inv_abs);
        float m3 = (float)(m2d * inv_vo);
        float m4 = (float)(m3d * inv_vo);
        float m5 = (float)(m4d * inv_vo);
        float m6 = (float)(m5d * inv_vo);

        float A = sax[0], B = saq[0], X = srx[0], Y = srq[0];
        float abs_loss = expf(-A) * m1 + A + expf(-B) * m2 + B;
        float vo_loss  = expf(-X) * m3 + X + expf(-Y) * m4 + Y;
        float imu_loss = expf(-X) * m5 + X + expf(-Y) * m6 + Y;
        out[0] = abs_loss + vo_loss + imu_loss;

        g_acc[0] = 0.0; g_acc[1] = 0.0; g_acc[2] = 0.0;
        g_acc[3] = 0.0; g_acc[4] = 0.0; g_acc[5] = 0.0;
        g_ticket = 0u;
        __threadfence();
    }
}

extern "C" void kernel_launch(void* const* d_in, const int* in_sizes, int n_in,
                              void* d_out, int out_size)
{
    const float* pred = (const float*)d_in[0];
    const float* targ = (const float*)d_in[1];
    const float* imu  = (const float*)d_in[2];
    const float* sax  = (const float*)d_in[3];
    const float* saq  = (const float*)d_in[4];
    const float* srx  = (const float*)d_in[5];
    const float* srq  = (const float*)d_in[6];

    const int T = 1024;
    const int total = in_sizes[0] / 6;          // N*T (even)
    const long long N = total / T;
    const int npairs = total >> 1;

    // Exactly one residency wave: 152 SMs x 2 CTAs/SM (<=128 regs/thread).
    int blocks = 152 * 2;
    int maxb = (npairs + 255) / 256;
    if (blocks > maxb) blocks = maxb;

    double inv_abs = 1.0 / ((double)total * 3.0);
    double inv_vo  = 1.0 / ((double)N * (double)(T - 1) * 3.0);

    loss_kernel<<<blocks, 256>>>(pred, targ, imu, sax, saq, srx, srq,
                                 (float*)d_out, npairs, inv_abs, inv_vo);
}